// round 16
// baseline (speedup 1.0000x reference)
#include <cuda_runtime.h>
#include <cuda_bf16.h>
#include <cuda_fp16.h>
#include <math.h>
#include <stdint.h>

#define EMBED 1024
#define NH 16
#define DK 64
#define BATCH 2
#define SEQ 2048
#define M_ROWS (BATCH*SEQ)      // 4096
#define QKV_COLS (3*EMBED)      // 3072

// log2(e) / sqrt(1024) — folded into Q at the QKV epilogue
#define QSCALE 0.0450842200f

// ---------------- scratch (__device__ globals) ------------------------------
__device__ __align__(16) __half g_x16[M_ROWS*EMBED];
__device__ __align__(16) __half g_wqkv16[QKV_COLS*EMBED];
__device__ __align__(16) __half g_wo16[EMBED*EMBED];

__device__ __align__(16) __half g_qf[BATCH*NH*SEQ*DK];   // [B,H,N,dk] (pre-scaled)
__device__ __align__(16) __half g_kf[BATCH*NH*SEQ*DK];   // [B,H,N,dk]
__device__ __align__(16) __half g_vtf[BATCH*NH*DK*SEQ];  // [B,H,dk,N] (transposed)

__device__ __align__(16) __half g_atf[M_ROWS*EMBED];     // attention out [B,N,C]

// ---------------- PTX helpers (plain-target, sm_80-class) -------------------
__device__ __forceinline__ uint32_t smem_u32(const void* p) {
    uint32_t a;
    asm("{ .reg .u64 t; cvta.to.shared.u64 t, %1; cvt.u32.u64 %0, t; }" : "=r"(a) : "l"(p));
    return a;
}
__device__ __forceinline__ void cp16(uint32_t dst, const void* src) {
    asm volatile("cp.async.cg.shared.global [%0], [%1], 16;" :: "r"(dst), "l"(src));
}
#define CP_COMMIT() asm volatile("cp.async.commit_group;" ::: "memory")
#define CP_WAIT0()  asm volatile("cp.async.wait_group 0;" ::: "memory")
#define CP_WAIT1()  asm volatile("cp.async.wait_group 1;" ::: "memory")

__device__ __forceinline__ void ldsm_x4(uint32_t* r, uint32_t addr) {
    asm volatile("ldmatrix.sync.aligned.m8n8.x4.shared.b16 {%0,%1,%2,%3}, [%4];"
                 : "=r"(r[0]), "=r"(r[1]), "=r"(r[2]), "=r"(r[3]) : "r"(addr));
}
__device__ __forceinline__ void mma_f16(float* c, const uint32_t* a, const uint32_t* b) {
    asm volatile(
        "mma.sync.aligned.m16n8k16.row.col.f32.f16.f16.f32 "
        "{%0,%1,%2,%3}, {%4,%5,%6,%7}, {%8,%9}, {%0,%1,%2,%3};"
        : "+f"(c[0]), "+f"(c[1]), "+f"(c[2]), "+f"(c[3])
        : "r"(a[0]), "r"(a[1]), "r"(a[2]), "r"(a[3]), "r"(b[0]), "r"(b[1]));
}
// packed fp16x2 exp2 — one MUFU op for two values (sm_75+)
__device__ __forceinline__ uint32_t ex2_h2(uint32_t x) {
    uint32_t y;
    asm("ex2.approx.f16x2 %0, %1;" : "=r"(y) : "r"(x));
    return y;
}

// 128B-row XOR swizzle (rows of 64 fp16 = 128B). chunk in 16B units (0..7).
__device__ __forceinline__ uint32_t swza(uint32_t base, int row, int chunk) {
    return base + row * 128 + ((chunk ^ (row & 7)) * 16);
}

// ---------------- fused conversion kernel ------------------------------------
#define NX4 (M_ROWS*EMBED/4)       // 1048576
#define NQ4 (QKV_COLS*EMBED/4)     // 786432
#define NO4 (EMBED*EMBED/4)        // 262144

__global__ void tohalf3_kernel(const float* __restrict__ x,
                               const float* __restrict__ wq,
                               const float* __restrict__ wo)
{
    int i = blockIdx.x * blockDim.x + threadIdx.x;
    const float* src; __half* dst; int j;
    if (i < NX4)            { src = x;  dst = g_x16;    j = i; }
    else if (i < NX4 + NQ4) { src = wq; dst = g_wqkv16; j = i - NX4; }
    else if (i < NX4 + NQ4 + NO4) { src = wo; dst = g_wo16; j = i - NX4 - NQ4; }
    else return;
    float4 f = ((const float4*)src)[j];
    ((__half2*)dst)[2*j]   = __floats2half2_rn(f.x, f.y);
    ((__half2*)dst)[2*j+1] = __floats2half2_rn(f.z, f.w);
}

// ---------------- fp16 single-pass GEMM (BK=64, 3-stage) --------------------
// CTA 128x128, 8 warps (2x4), warp tile 64x32, 256 threads.
// EPI=0: QKV scatter -> q/k fp16 (q pre-scaled) + v^T fp16
// EPI=1: out-proj -> fp32 Cout
#define BK 64
#define HTILE_B (128 * BK * 2)          // 16384 bytes (fp16 tile, 128B rows)
#define HSTAGE_B (2 * HTILE_B)          // 32768
#define SMEM_HGEMM (3 * HSTAGE_B)       // 98304

template<int EPI>
__global__ void __launch_bounds__(256)
hgemm(const __half* __restrict__ A, const __half* __restrict__ B,
      const float* __restrict__ bias, float* __restrict__ Cout)
{
    extern __shared__ char smem[];
    const uint32_t sb = smem_u32(smem);

    const int tid = threadIdx.x;
    const int bm = blockIdx.y * 128;
    const int bn = blockIdx.x * 128;

    const int tile = tid >> 7;           // 0=A 1=B
    const int slane = tid & 127;
    const __half* sbase = tile ? (B + (size_t)bn * EMBED)
                               : (A + (size_t)bm * EMBED);

    const int wid = tid >> 5;
    const int lane = tid & 31;
    const int wm = (wid >> 2) * 64;
    const int wn = (wid & 3) * 32;

    float acc[4][4][4];
#pragma unroll
    for (int i = 0; i < 4; i++)
#pragma unroll
        for (int j = 0; j < 4; j++)
#pragma unroll
            for (int t = 0; t < 4; t++) acc[i][j][t] = 0.f;

    const int NCHUNK = EMBED / BK;   // 16

    auto issue = [&](int c, int s) {
        const uint32_t tb = sb + s * HSTAGE_B + tile * HTILE_B;
        const int k0 = c * BK;
#pragma unroll
        for (int t = 0; t < 8; t++) {
            const int w = slane + t * 128;     // 0..1023 16B-chunks per tile
            const int r = w >> 3;              // row 0..127
            const int cc = w & 7;              // chunk 0..7
            cp16(swza(tb, r, cc), sbase + (size_t)r * EMBED + k0 + cc * 8);
        }
        CP_COMMIT();
    };

    issue(0, 0);
    issue(1, 1);

    // fragment addressing
    const int arow = wm + (lane & 15);
    const int ach  = lane >> 4;                          // 0/1
    const int brow4 = wn + (lane & 7) + ((lane >> 4) & 1) * 8;   // x4 B: n-row
    const int bch4  = (lane >> 3) & 1;                   // k-half select

    int s = 0;
    for (int c = 0; c < NCHUNK; c++) {
        CP_WAIT1();
        __syncthreads();
        if (c + 2 < NCHUNK) issue(c + 2, (c + 2) % 3);

        const uint32_t sA = sb + s * HSTAGE_B;
        const uint32_t sB = sA + HTILE_B;

#pragma unroll
        for (int ks = 0; ks < 4; ks++) {       // 4 k-steps of 16 within BK=64
            uint32_t af[4][4], bf[2][4];
#pragma unroll
            for (int mt = 0; mt < 4; mt++)
                ldsm_x4(af[mt], swza(sA, arow + mt * 16, ks * 2 + ach));
#pragma unroll
            for (int j = 0; j < 2; j++)
                ldsm_x4(bf[j], swza(sB, brow4 + j * 16, ks * 2 + bch4));
#pragma unroll
            for (int mt = 0; mt < 4; mt++)
#pragma unroll
                for (int j = 0; j < 2; j++) {
                    mma_f16(acc[mt][2*j + 0], af[mt], bf[j] + 0);
                    mma_f16(acc[mt][2*j + 1], af[mt], bf[j] + 2);
                }
        }
        s = (s + 1 == 3) ? 0 : s + 1;
    }

#pragma unroll
    for (int mt = 0; mt < 4; mt++) {
#pragma unroll
        for (int half = 0; half < 2; half++) {
            const int m = bm + wm + mt * 16 + (lane >> 2) + half * 8;
            const int bi = m >> 11;
            const int tt = m & 2047;
#pragma unroll
            for (int nt = 0; nt < 4; nt++) {
                const int n0 = bn + wn + nt * 8 + (lane & 3) * 2;
                float v0 = acc[mt][nt][half * 2 + 0] + bias[n0];
                float v1 = acc[mt][nt][half * 2 + 1] + bias[n0 + 1];
                if (EPI == 0) {
                    const int which = n0 >> 10;
                    const int cc = n0 & 1023;
                    const int h = cc >> 6;
                    const int d = cc & 63;
                    const int bh = bi * NH + h;
                    if (which == 0) { v0 *= QSCALE; v1 *= QSCALE; }
                    if (which < 2) {
                        __half* dst = which ? g_kf : g_qf;
                        const size_t idx = ((size_t)bh * SEQ + tt) * DK + d;
                        *(__half2*)(dst + idx) = __floats2half2_rn(v0, v1);
                    } else {
                        const size_t idx = ((size_t)bh * DK + d) * SEQ + tt;
                        g_vtf[idx]       = __float2half_rn(v0);
                        g_vtf[idx + SEQ] = __float2half_rn(v1);
                    }
                } else {
                    Cout[(size_t)m * EMBED + n0]     = v0;
                    Cout[(size_t)m * EMBED + n0 + 1] = v1;
                }
            }
        }
    }
}

// ---------------- tensor-core causal flash attention -------------------------
// Fixed-max softmax + f16x2 exp2 + LAGGED PV: PV of tile kt runs in iteration
// kt+1, so the softmax chain has a full iteration of slack and the exposed
// per-tile path is pure MMA + one barrier. 4 stages keep V(kt-1) alive.
// CTA: 64 queries (4 warps x 16 rows), 64-key tiles.
// smem: Q (8K) + 4 stages x {K(8K), VT(8K)} = 72K -> 3 CTAs/SM
#define ATT_NSTAGE 4
#define ATT_SMEM (8192 + ATT_NSTAGE * 16384)

__global__ void __launch_bounds__(128) attn_mma()
{
    extern __shared__ char smem[];
    const uint32_t sb = smem_u32(smem);
    const uint32_t q_s = sb;
    const uint32_t stage0 = sb + 8192;

    const int tid = threadIdx.x;
    const int lane = tid & 31;
    const int wid = tid >> 5;
    const int g = lane >> 2;
    const int tg = lane & 3;
    const int bh = blockIdx.y;
    const int qb = (int)(gridDim.x - 1 - blockIdx.x);   // heavy blocks first

    const __half* q_g  = g_qf  + ((size_t)bh * SEQ + qb * 64) * DK;
    const __half* k_g  = g_kf  + (size_t)bh * SEQ * DK;
    const __half* vt_g = g_vtf + (size_t)bh * DK * SEQ;

#pragma unroll
    for (int i = 0; i < 4; i++) {
        const int w = tid + i * 128;
        const int r = w >> 3, c = w & 7;
        cp16(swza(q_s, r, c), q_g + (size_t)r * DK + c * 8);
    }
    CP_COMMIT();

    auto issue_tile = [&](int kt, int s) {
        const uint32_t st = stage0 + s * 16384;
        const int k0 = kt * 64;
#pragma unroll
        for (int i = 0; i < 4; i++) {
            const int w = tid + i * 128;
            const int r = w >> 3, c = w & 7;
            cp16(swza(st, r, c),        k_g + (size_t)(k0 + r) * DK + c * 8);
            cp16(swza(st + 8192, r, c), vt_g + (size_t)r * SEQ + k0 + c * 8);
        }
        CP_COMMIT();
    };

    const int ntiles = qb + 1;
    issue_tile(0, 0);
    if (ntiles > 1) issue_tile(1, 1);

    uint32_t qf[4][4];
    float oacc[8][4];
#pragma unroll
    for (int nt = 0; nt < 8; nt++)
#pragma unroll
        for (int t = 0; t < 4; t++) oacc[nt][t] = 0.f;
    float l0 = 0.f, l1 = 0.f;

    // x4 fragment addressing for K/V (two n8-tiles per op)
    const int brow4 = (lane & 7) + ((lane >> 4) & 1) * 8;
    const int bch4  = (lane >> 3) & 1;

    uint32_t pf[4][4];           // P fragment of tile kt-1 (lagged across iters)

    auto do_pv = [&](uint32_t sVT) {
#pragma unroll
        for (int kc = 0; kc < 4; kc++) {
            uint32_t vf[4][4];
#pragma unroll
            for (int j = 0; j < 4; j++)
                ldsm_x4(vf[j], swza(sVT, j * 16 + brow4, kc * 2 + bch4));
#pragma unroll
            for (int j = 0; j < 4; j++) {
                mma_f16(oacc[2*j + 0], pf[kc], vf[j] + 0);
                mma_f16(oacc[2*j + 1], pf[kc], vf[j] + 2);
            }
        }
    };

    int s = 0, sprev = 0;
    for (int kt = 0; kt < ntiles; kt++) {
        if (kt + 1 < ntiles) CP_WAIT1();
        else                 CP_WAIT0();
        __syncthreads();     // tile kt visible; stage (kt+2)%4 free; all warps
                             // done with PV(kt-2) -> stage (kt+2)%4 reusable
        if (kt + 2 < ntiles) issue_tile(kt + 2, (kt + 2) % ATT_NSTAGE);

        if (kt == 0) {
            const int arow = wid * 16 + (lane & 15);
            const int ach = lane >> 4;
#pragma unroll
            for (int kc = 0; kc < 4; kc++)
                ldsm_x4(qf[kc], swza(q_s, arow, kc * 2 + ach));
        }

        const uint32_t sK = stage0 + s * 16384;

        // ---- QK(kt) ----
        float sacc[8][4];
#pragma unroll
        for (int nt = 0; nt < 8; nt++)
#pragma unroll
            for (int t = 0; t < 4; t++) sacc[nt][t] = 0.f;

#pragma unroll
        for (int kc = 0; kc < 4; kc++) {
            uint32_t bf[4][4];
#pragma unroll
            for (int j = 0; j < 4; j++)
                ldsm_x4(bf[j], swza(sK, j * 16 + brow4, kc * 2 + bch4));
#pragma unroll
            for (int j = 0; j < 4; j++) {
                mma_f16(sacc[2*j + 0], qf[kc], bf[j] + 0);
                mma_f16(sacc[2*j + 1], qf[kc], bf[j] + 2);
            }
        }

        // ---- PV(kt-1): independent of QK(kt); softmax(kt-1) had a full
        //      iteration to complete ----
        if (kt > 0) do_pv(stage0 + sprev * 16384 + 8192);

        // ---- causal mask (diagonal tile) ----
        if (kt == qb) {
#pragma unroll
            for (int nt = 0; nt < 8; nt++)
#pragma unroll
                for (int idx = 0; idx < 4; idx++) {
                    const int key = nt * 8 + tg * 2 + (idx & 1);
                    const int qr  = wid * 16 + g + (idx >> 1) * 8;
                    if (key > qr) sacc[nt][idx] = -1e30f;
                }
        }

        // ---- fixed-max softmax via packed fp16x2 exp2 -> pf (for next iter) --
#pragma unroll
        for (int nt = 0; nt < 8; nt++) {
            __half2 s01 = __floats2half2_rn(sacc[nt][0], sacc[nt][1]);
            __half2 s23 = __floats2half2_rn(sacc[nt][2], sacc[nt][3]);
            const uint32_t p01 = ex2_h2(*(uint32_t*)&s01);
            const uint32_t p23 = ex2_h2(*(uint32_t*)&s23);
            float2 f01 = __half22float2(*(__half2*)&p01);
            float2 f23 = __half22float2(*(__half2*)&p23);
            l0 += f01.x + f01.y;
            l1 += f23.x + f23.y;
            const int kc = nt >> 1;
            const int r = (nt & 1) * 2;
            pf[kc][r + 0] = p01;
            pf[kc][r + 1] = p23;
        }

        sprev = s;
        s = (s + 1 == ATT_NSTAGE) ? 0 : s + 1;
    }

    // ---- final PV of the last tile (stage sprev untouched after loop) ----
    do_pv(stage0 + sprev * 16384 + 8192);

    // ---- single final quad-reduce of the row sums ----
    l0 += __shfl_xor_sync(0xffffffffu, l0, 1);
    l0 += __shfl_xor_sync(0xffffffffu, l0, 2);
    l1 += __shfl_xor_sync(0xffffffffu, l1, 1);
    l1 += __shfl_xor_sync(0xffffffffu, l1, 2);

    // ---- normalize + write fp16 [B,N,C] ----
    const float inv0 = 1.0f / l0;
    const float inv1 = 1.0f / l1;
    const int bi = bh >> 4;
    const int h  = bh & 15;
    const int row0 = bi * SEQ + qb * 64 + wid * 16 + g;
#pragma unroll
    for (int nt = 0; nt < 8; nt++) {
        const int col = h * 64 + nt * 8 + tg * 2;
        *(__half2*)(g_atf + (size_t)row0 * EMBED + col) =
            __floats2half2_rn(oacc[nt][0] * inv0, oacc[nt][1] * inv0);
        *(__half2*)(g_atf + (size_t)(row0 + 8) * EMBED + col) =
            __floats2half2_rn(oacc[nt][2] * inv1, oacc[nt][3] * inv1);
    }
}

// ---------------------------------------------------------------------------
extern "C" void kernel_launch(void* const* d_in, const int* in_sizes, int n_in,
                              void* d_out, int out_size)
{
    const float* x     = (const float*)d_in[0];
    const float* w_qkv = (const float*)d_in[1];
    const float* b_qkv = (const float*)d_in[2];
    const float* w_o   = (const float*)d_in[3];
    const float* b_o   = (const float*)d_in[4];
    float* out = (float*)d_out;

    void *x16, *wq16, *wo16, *at16;
    cudaGetSymbolAddress(&x16, g_x16);
    cudaGetSymbolAddress(&wq16, g_wqkv16);
    cudaGetSymbolAddress(&wo16, g_wo16);
    cudaGetSymbolAddress(&at16, g_atf);

    cudaFuncSetAttribute(hgemm<0>, cudaFuncAttributeMaxDynamicSharedMemorySize, SMEM_HGEMM);
    cudaFuncSetAttribute(hgemm<1>, cudaFuncAttributeMaxDynamicSharedMemorySize, SMEM_HGEMM);
    cudaFuncSetAttribute(attn_mma, cudaFuncAttributeMaxDynamicSharedMemorySize, ATT_SMEM);

    // fused fp32 -> fp16 conversions
    {
        const int ntot = NX4 + NQ4 + NO4;
        tohalf3_kernel<<<(ntot + 255) / 256, 256>>>(x, w_qkv, w_o);
    }

    // QKV projection (fp16, BK=64) -> q/k fp16 + v^T fp16
    hgemm<0><<<dim3(QKV_COLS / 128, M_ROWS / 128), 256, SMEM_HGEMM>>>(
        (const __half*)x16, (const __half*)wq16, b_qkv, nullptr);

    // tensor-core flash attention (fp16, lagged-PV pipeline) -> g_atf
    attn_mma<<<dim3(SEQ / 64, BATCH * NH), 128, ATT_SMEM>>>();

    // output projection (fp16, BK=64) -> d_out
    hgemm<1><<<dim3(EMBED / 128, M_ROWS / 128), 256, SMEM_HGEMM>>>(
        (const __half*)at16, (const __half*)wo16, b_o, out);
}

// round 17
// speedup vs baseline: 1.0090x; 1.0090x over previous
#include <cuda_runtime.h>
#include <cuda_bf16.h>
#include <cuda_fp16.h>
#include <math.h>
#include <stdint.h>

#define EMBED 1024
#define NH 16
#define DK 64
#define BATCH 2
#define SEQ 2048
#define M_ROWS (BATCH*SEQ)      // 4096
#define QKV_COLS (3*EMBED)      // 3072

// log2(e) / sqrt(1024) — folded into Q at the QKV epilogue
#define QSCALE 0.0450842200f

// ---------------- scratch (__device__ globals) ------------------------------
__device__ __align__(16) __half g_x16[M_ROWS*EMBED];
__device__ __align__(16) __half g_wqkv16[QKV_COLS*EMBED];
__device__ __align__(16) __half g_wo16[EMBED*EMBED];

__device__ __align__(16) __half g_qf[BATCH*NH*SEQ*DK];   // [B,H,N,dk] (pre-scaled)
__device__ __align__(16) __half g_kf[BATCH*NH*SEQ*DK];   // [B,H,N,dk]
__device__ __align__(16) __half g_vtf[BATCH*NH*DK*SEQ];  // [B,H,dk,N] (transposed)

__device__ __align__(16) __half g_atf[M_ROWS*EMBED];     // attention out [B,N,C]

// ---------------- PTX helpers (plain-target, sm_80-class) -------------------
__device__ __forceinline__ uint32_t smem_u32(const void* p) {
    uint32_t a;
    asm("{ .reg .u64 t; cvta.to.shared.u64 t, %1; cvt.u32.u64 %0, t; }" : "=r"(a) : "l"(p));
    return a;
}
__device__ __forceinline__ void cp16(uint32_t dst, const void* src) {
    asm volatile("cp.async.cg.shared.global [%0], [%1], 16;" :: "r"(dst), "l"(src));
}
#define CP_COMMIT() asm volatile("cp.async.commit_group;" ::: "memory")
#define CP_WAIT0()  asm volatile("cp.async.wait_group 0;" ::: "memory")
#define CP_WAIT1()  asm volatile("cp.async.wait_group 1;" ::: "memory")

__device__ __forceinline__ void ldsm_x4(uint32_t* r, uint32_t addr) {
    asm volatile("ldmatrix.sync.aligned.m8n8.x4.shared.b16 {%0,%1,%2,%3}, [%4];"
                 : "=r"(r[0]), "=r"(r[1]), "=r"(r[2]), "=r"(r[3]) : "r"(addr));
}
__device__ __forceinline__ void mma_f16(float* c, const uint32_t* a, const uint32_t* b) {
    asm volatile(
        "mma.sync.aligned.m16n8k16.row.col.f32.f16.f16.f32 "
        "{%0,%1,%2,%3}, {%4,%5,%6,%7}, {%8,%9}, {%0,%1,%2,%3};"
        : "+f"(c[0]), "+f"(c[1]), "+f"(c[2]), "+f"(c[3])
        : "r"(a[0]), "r"(a[1]), "r"(a[2]), "r"(a[3]), "r"(b[0]), "r"(b[1]));
}
// packed fp16x2 exp2 — one MUFU op for two values (sm_75+)
__device__ __forceinline__ uint32_t ex2_h2(uint32_t x) {
    uint32_t y;
    asm("ex2.approx.f16x2 %0, %1;" : "=r"(y) : "r"(x));
    return y;
}

// 128B-row XOR swizzle (rows of 64 fp16 = 128B). chunk in 16B units (0..7).
__device__ __forceinline__ uint32_t swza(uint32_t base, int row, int chunk) {
    return base + row * 128 + ((chunk ^ (row & 7)) * 16);
}

// ---------------- fused conversion kernel ------------------------------------
#define NX4 (M_ROWS*EMBED/4)       // 1048576
#define NQ4 (QKV_COLS*EMBED/4)     // 786432
#define NO4 (EMBED*EMBED/4)        // 262144

__global__ void tohalf3_kernel(const float* __restrict__ x,
                               const float* __restrict__ wq,
                               const float* __restrict__ wo)
{
    int i = blockIdx.x * blockDim.x + threadIdx.x;
    const float* src; __half* dst; int j;
    if (i < NX4)            { src = x;  dst = g_x16;    j = i; }
    else if (i < NX4 + NQ4) { src = wq; dst = g_wqkv16; j = i - NX4; }
    else if (i < NX4 + NQ4 + NO4) { src = wo; dst = g_wo16; j = i - NX4 - NQ4; }
    else return;
    float4 f = ((const float4*)src)[j];
    ((__half2*)dst)[2*j]   = __floats2half2_rn(f.x, f.y);
    ((__half2*)dst)[2*j+1] = __floats2half2_rn(f.z, f.w);
}

// ---------------- fp16 single-pass GEMM (BK=64, 3-stage) --------------------
// CTA 128x128, 8 warps (2x4), warp tile 64x32, 256 threads, 2 CTAs/SM pinned.
// EPI=0: QKV scatter -> q/k fp16 (q pre-scaled) + v^T fp16
// EPI=1: out-proj -> fp32 Cout
#define BK 64
#define HTILE_B (128 * BK * 2)          // 16384 bytes (fp16 tile, 128B rows)
#define HSTAGE_B (2 * HTILE_B)          // 32768
#define SMEM_HGEMM (3 * HSTAGE_B)       // 98304

template<int EPI>
__global__ void __launch_bounds__(256, 2)
hgemm(const __half* __restrict__ A, const __half* __restrict__ B,
      const float* __restrict__ bias, float* __restrict__ Cout)
{
    extern __shared__ char smem[];
    const uint32_t sb = smem_u32(smem);

    const int tid = threadIdx.x;
    const int bm = blockIdx.y * 128;
    const int bn = blockIdx.x * 128;

    const int tile = tid >> 7;           // 0=A 1=B
    const int slane = tid & 127;
    const __half* sbase = tile ? (B + (size_t)bn * EMBED)
                               : (A + (size_t)bm * EMBED);

    const int wid = tid >> 5;
    const int lane = tid & 31;
    const int wm = (wid >> 2) * 64;
    const int wn = (wid & 3) * 32;

    float acc[4][4][4];
#pragma unroll
    for (int i = 0; i < 4; i++)
#pragma unroll
        for (int j = 0; j < 4; j++)
#pragma unroll
            for (int t = 0; t < 4; t++) acc[i][j][t] = 0.f;

    const int NCHUNK = EMBED / BK;   // 16

    auto issue = [&](int c, int s) {
        const uint32_t tb = sb + s * HSTAGE_B + tile * HTILE_B;
        const int k0 = c * BK;
#pragma unroll
        for (int t = 0; t < 8; t++) {
            const int w = slane + t * 128;     // 0..1023 16B-chunks per tile
            const int r = w >> 3;              // row 0..127
            const int cc = w & 7;              // chunk 0..7
            cp16(swza(tb, r, cc), sbase + (size_t)r * EMBED + k0 + cc * 8);
        }
        CP_COMMIT();
    };

    issue(0, 0);
    issue(1, 1);

    // fragment addressing
    const int arow = wm + (lane & 15);
    const int ach  = lane >> 4;                          // 0/1
    const int brow4 = wn + (lane & 7) + ((lane >> 4) & 1) * 8;   // x4 B: n-row
    const int bch4  = (lane >> 3) & 1;                   // k-half select

    int s = 0;
    for (int c = 0; c < NCHUNK; c++) {
        CP_WAIT1();
        __syncthreads();
        if (c + 2 < NCHUNK) issue(c + 2, (c + 2) % 3);

        const uint32_t sA = sb + s * HSTAGE_B;
        const uint32_t sB = sA + HTILE_B;

#pragma unroll
        for (int ks = 0; ks < 4; ks++) {       // 4 k-steps of 16 within BK=64
            uint32_t af[4][4], bf[2][4];
#pragma unroll
            for (int mt = 0; mt < 4; mt++)
                ldsm_x4(af[mt], swza(sA, arow + mt * 16, ks * 2 + ach));
#pragma unroll
            for (int j = 0; j < 2; j++)
                ldsm_x4(bf[j], swza(sB, brow4 + j * 16, ks * 2 + bch4));
#pragma unroll
            for (int mt = 0; mt < 4; mt++)
#pragma unroll
                for (int j = 0; j < 2; j++) {
                    mma_f16(acc[mt][2*j + 0], af[mt], bf[j] + 0);
                    mma_f16(acc[mt][2*j + 1], af[mt], bf[j] + 2);
                }
        }
        s = (s + 1 == 3) ? 0 : s + 1;
    }

#pragma unroll
    for (int mt = 0; mt < 4; mt++) {
#pragma unroll
        for (int half = 0; half < 2; half++) {
            const int m = bm + wm + mt * 16 + (lane >> 2) + half * 8;
            const int bi = m >> 11;
            const int tt = m & 2047;
#pragma unroll
            for (int nt = 0; nt < 4; nt++) {
                const int n0 = bn + wn + nt * 8 + (lane & 3) * 2;
                float v0 = acc[mt][nt][half * 2 + 0] + bias[n0];
                float v1 = acc[mt][nt][half * 2 + 1] + bias[n0 + 1];
                if (EPI == 0) {
                    const int which = n0 >> 10;
                    const int cc = n0 & 1023;
                    const int h = cc >> 6;
                    const int d = cc & 63;
                    const int bh = bi * NH + h;
                    if (which == 0) { v0 *= QSCALE; v1 *= QSCALE; }
                    if (which < 2) {
                        __half* dst = which ? g_kf : g_qf;
                        const size_t idx = ((size_t)bh * SEQ + tt) * DK + d;
                        *(__half2*)(dst + idx) = __floats2half2_rn(v0, v1);
                    } else {
                        const size_t idx = ((size_t)bh * DK + d) * SEQ + tt;
                        g_vtf[idx]       = __float2half_rn(v0);
                        g_vtf[idx + SEQ] = __float2half_rn(v1);
                    }
                } else {
                    Cout[(size_t)m * EMBED + n0]     = v0;
                    Cout[(size_t)m * EMBED + n0 + 1] = v1;
                }
            }
        }
    }
}

// ---------------- tensor-core causal flash attention -------------------------
// R15 structure: fixed-max softmax + packed fp16x2 exp2, immediate PV,
// 3-stage cp.async, ONE barrier per tile. 4 CTAs/SM pinned via launch bounds
// (smem 8K + 3x16K = 56K allows 4; reg cap 128 enforced).
#define ATT_SMEM (8192 + 3 * 16384)

__global__ void __launch_bounds__(128, 4) attn_mma()
{
    extern __shared__ char smem[];
    const uint32_t sb = smem_u32(smem);
    const uint32_t q_s = sb;
    const uint32_t stage0 = sb + 8192;

    const int tid = threadIdx.x;
    const int lane = tid & 31;
    const int wid = tid >> 5;
    const int g = lane >> 2;
    const int tg = lane & 3;
    const int bh = blockIdx.y;
    const int qb = (int)(gridDim.x - 1 - blockIdx.x);   // heavy blocks first

    const __half* q_g  = g_qf  + ((size_t)bh * SEQ + qb * 64) * DK;
    const __half* k_g  = g_kf  + (size_t)bh * SEQ * DK;
    const __half* vt_g = g_vtf + (size_t)bh * DK * SEQ;

#pragma unroll
    for (int i = 0; i < 4; i++) {
        const int w = tid + i * 128;
        const int r = w >> 3, c = w & 7;
        cp16(swza(q_s, r, c), q_g + (size_t)r * DK + c * 8);
    }
    CP_COMMIT();

    auto issue_tile = [&](int kt, int s) {
        const uint32_t st = stage0 + s * 16384;
        const int k0 = kt * 64;
#pragma unroll
        for (int i = 0; i < 4; i++) {
            const int w = tid + i * 128;
            const int r = w >> 3, c = w & 7;
            cp16(swza(st, r, c),        k_g + (size_t)(k0 + r) * DK + c * 8);
            cp16(swza(st + 8192, r, c), vt_g + (size_t)r * SEQ + k0 + c * 8);
        }
        CP_COMMIT();
    };

    const int ntiles = qb + 1;
    issue_tile(0, 0);
    if (ntiles > 1) issue_tile(1, 1);

    uint32_t qf[4][4];
    float oacc[8][4];
#pragma unroll
    for (int nt = 0; nt < 8; nt++)
#pragma unroll
        for (int t = 0; t < 4; t++) oacc[nt][t] = 0.f;
    float l0 = 0.f, l1 = 0.f;   // plain sums (fixed-max softmax)

    // x4 fragment addressing for K/V (two n8-tiles per op)
    const int brow4 = (lane & 7) + ((lane >> 4) & 1) * 8;
    const int bch4  = (lane >> 3) & 1;

    int s = 0;
    for (int kt = 0; kt < ntiles; kt++) {
        if (kt + 1 < ntiles) CP_WAIT1();
        else                 CP_WAIT0();
        __syncthreads();
        if (kt + 2 < ntiles) issue_tile(kt + 2, (kt + 2) % 3);

        if (kt == 0) {
            const int arow = wid * 16 + (lane & 15);
            const int ach = lane >> 4;
#pragma unroll
            for (int kc = 0; kc < 4; kc++)
                ldsm_x4(qf[kc], swza(q_s, arow, kc * 2 + ach));
        }

        const uint32_t sK  = stage0 + s * 16384;
        const uint32_t sVT = sK + 8192;

        float sacc[8][4];
#pragma unroll
        for (int nt = 0; nt < 8; nt++)
#pragma unroll
            for (int t = 0; t < 4; t++) sacc[nt][t] = 0.f;

#pragma unroll
        for (int kc = 0; kc < 4; kc++) {
            uint32_t bf[4][4];
#pragma unroll
            for (int j = 0; j < 4; j++)
                ldsm_x4(bf[j], swza(sK, j * 16 + brow4, kc * 2 + bch4));
#pragma unroll
            for (int j = 0; j < 4; j++) {
                mma_f16(sacc[2*j + 0], qf[kc], bf[j] + 0);
                mma_f16(sacc[2*j + 1], qf[kc], bf[j] + 2);
            }
        }

        if (kt == qb) {
#pragma unroll
            for (int nt = 0; nt < 8; nt++)
#pragma unroll
                for (int idx = 0; idx < 4; idx++) {
                    const int key = nt * 8 + tg * 2 + (idx & 1);
                    const int qr  = wid * 16 + g + (idx >> 1) * 8;
                    if (key > qr) sacc[nt][idx] = -1e30f;
                }
        }

        // ---- fixed-max softmax via packed fp16x2 exp2 ----
        uint32_t pf[4][4];
#pragma unroll
        for (int nt = 0; nt < 8; nt++) {
            __half2 s01 = __floats2half2_rn(sacc[nt][0], sacc[nt][1]);
            __half2 s23 = __floats2half2_rn(sacc[nt][2], sacc[nt][3]);
            const uint32_t p01 = ex2_h2(*(uint32_t*)&s01);
            const uint32_t p23 = ex2_h2(*(uint32_t*)&s23);
            float2 f01 = __half22float2(*(__half2*)&p01);
            float2 f23 = __half22float2(*(__half2*)&p23);
            l0 += f01.x + f01.y;
            l1 += f23.x + f23.y;
            const int kc = nt >> 1;
            const int r = (nt & 1) * 2;
            pf[kc][r + 0] = p01;
            pf[kc][r + 1] = p23;
        }

#pragma unroll
        for (int kc = 0; kc < 4; kc++) {
            uint32_t vf[4][4];
#pragma unroll
            for (int j = 0; j < 4; j++)
                ldsm_x4(vf[j], swza(sVT, j * 16 + brow4, kc * 2 + bch4));
#pragma unroll
            for (int j = 0; j < 4; j++) {
                mma_f16(oacc[2*j + 0], pf[kc], vf[j] + 0);
                mma_f16(oacc[2*j + 1], pf[kc], vf[j] + 2);
            }
        }
        s = (s + 1 == 3) ? 0 : s + 1;
    }

    // ---- single final quad-reduce of the row sums ----
    l0 += __shfl_xor_sync(0xffffffffu, l0, 1);
    l0 += __shfl_xor_sync(0xffffffffu, l0, 2);
    l1 += __shfl_xor_sync(0xffffffffu, l1, 1);
    l1 += __shfl_xor_sync(0xffffffffu, l1, 2);

    // ---- normalize + write fp16 [B,N,C] ----
    const float inv0 = 1.0f / l0;
    const float inv1 = 1.0f / l1;
    const int bi = bh >> 4;
    const int h  = bh & 15;
    const int row0 = bi * SEQ + qb * 64 + wid * 16 + g;
#pragma unroll
    for (int nt = 0; nt < 8; nt++) {
        const int col = h * 64 + nt * 8 + tg * 2;
        *(__half2*)(g_atf + (size_t)row0 * EMBED + col) =
            __floats2half2_rn(oacc[nt][0] * inv0, oacc[nt][1] * inv0);
        *(__half2*)(g_atf + (size_t)(row0 + 8) * EMBED + col) =
            __floats2half2_rn(oacc[nt][2] * inv1, oacc[nt][3] * inv1);
    }
}

// ---------------------------------------------------------------------------
extern "C" void kernel_launch(void* const* d_in, const int* in_sizes, int n_in,
                              void* d_out, int out_size)
{
    const float* x     = (const float*)d_in[0];
    const float* w_qkv = (const float*)d_in[1];
    const float* b_qkv = (const float*)d_in[2];
    const float* w_o   = (const float*)d_in[3];
    const float* b_o   = (const float*)d_in[4];
    float* out = (float*)d_out;

    void *x16, *wq16, *wo16, *at16;
    cudaGetSymbolAddress(&x16, g_x16);
    cudaGetSymbolAddress(&wq16, g_wqkv16);
    cudaGetSymbolAddress(&wo16, g_wo16);
    cudaGetSymbolAddress(&at16, g_atf);

    cudaFuncSetAttribute(hgemm<0>, cudaFuncAttributeMaxDynamicSharedMemorySize, SMEM_HGEMM);
    cudaFuncSetAttribute(hgemm<1>, cudaFuncAttributeMaxDynamicSharedMemorySize, SMEM_HGEMM);
    cudaFuncSetAttribute(attn_mma, cudaFuncAttributeMaxDynamicSharedMemorySize, ATT_SMEM);

    // fused fp32 -> fp16 conversions
    {
        const int ntot = NX4 + NQ4 + NO4;
        tohalf3_kernel<<<(ntot + 255) / 256, 256>>>(x, w_qkv, w_o);
    }

    // QKV projection (fp16, BK=64) -> q/k fp16 + v^T fp16
    hgemm<0><<<dim3(QKV_COLS / 128, M_ROWS / 128), 256, SMEM_HGEMM>>>(
        (const __half*)x16, (const __half*)wq16, b_qkv, nullptr);

    // tensor-core flash attention (fp16) -> g_atf
    attn_mma<<<dim3(SEQ / 64, BATCH * NH), 128, ATT_SMEM>>>();

    // output projection (fp16, BK=64) -> d_out
    hgemm<1><<<dim3(EMBED / 128, M_ROWS / 128), 256, SMEM_HGEMM>>>(
        (const __half*)at16, (const __half*)wo16, b_o, out);
}